// round 10
// baseline (speedup 1.0000x reference)
#include <cuda_runtime.h>
#include <cstdint>

#define NN3 262144
#define NN2 65536
#define NN1 16384

// Scratch (static device globals; no allocation allowed)
__device__ __align__(256) float g_x8 [NN3*16];
__device__ __align__(256) float g_x7p[NN2*16];
__device__ __align__(256) float g_x7 [NN2*32];
__device__ __align__(256) float g_x6p[NN1*32];
__device__ __align__(256) float g_x6 [NN1*64];
__device__ __align__(256) float g_x7d[NN2*32];
__device__ __align__(256) float g_x8d[NN3*16];

// zero row for -1 neighbors (explicit init -> guaranteed zeros in image)
__device__ __align__(16) float g_zero[64] = {0.f};

// ---------------- packed f32x2 helpers ----------------
__device__ __forceinline__ unsigned long long pack2(float x, float y) {
    unsigned long long r;
    asm("mov.b64 %0, {%1, %2};" : "=l"(r) : "f"(x), "f"(y));
    return r;
}
__device__ __forceinline__ void unpack2(float& x, float& y, unsigned long long v) {
    asm("mov.b64 {%0, %1}, %2;" : "=f"(x), "=f"(y) : "l"(v));
}
__device__ __forceinline__ void ffma2(unsigned long long& d, unsigned long long a, unsigned long long b) {
    asm("fma.rn.f32x2 %0, %1, %2, %0;" : "+l"(d) : "l"(a), "l"(b));
}

// =====================================================================
// conv5_k: register-resident gather GEMM.
//   - ALL weights (9 neighbors) staged transposed into smem ONCE;
//     exactly one __syncthreads in the whole kernel.
//   - feature quads LDG.128'd directly from L2 into registers
//     (no cp.async, no col smem, no double buffering, no per-stage barriers)
//   - MOV-free fma.rn.f32x2 accumulation (weights read as aligned u64 pairs)
// Thread map: og = tid % OUTG (8 outputs c0..c0+7), g = tid / OUTG (node lane);
//             MT nodes per thread at stride NG.
// out[n,c] = relu( sum_j sum_ci feat[(neigh[n,j])>>SHIFT, ci] * w[c, j*CIN+ci] + b[c] )
// =====================================================================
template<int CIN,int COUT,int NT,int MT,int SHIFT,bool RELU>
__global__ __launch_bounds__(NT, 2)
void conv5_k(const float* __restrict__ feat, const int* __restrict__ neigh,
             const float* __restrict__ w, const float* __restrict__ b,
             float* __restrict__ out)
{
    constexpr int NTC   = 8;
    constexpr int OUTG  = COUT / NTC;
    constexpr int NG    = NT / OUTG;
    constexpr int TILE  = MT * NG;
    constexpr int KFULL = 9 * CIN;
    constexpr int SW    = COUT + 4;            // smem weight row stride; (SW*4)%16==0
    static_assert((SW % 4) == 0, "weight row must stay 16B aligned");
    constexpr int CV    = CIN / 4;             // float4 per feature row
    constexpr int CH    = (CV > 8) ? 8 : CV;   // float4 per load chunk
    constexpr int NCH   = CV / CH;
    static_assert((KFULL*COUT) % NT == 0, "weight staging divisibility");

    extern __shared__ float swt[];             // [KFULL][SW] transposed weights

    const int tid  = threadIdx.x;
    const int base = blockIdx.x * TILE;

    // ---- stage ALL weights transposed (coalesced gmem read) ----
    #pragma unroll 4
    for (int i = tid; i < KFULL*COUT; i += NT) {
        int c = i / KFULL, k = i % KFULL;
        swt[k*SW + c] = w[i];
    }

    const int og = tid % OUTG;
    const int g  = tid / OUTG;
    const int c0 = og * NTC;

    // ---- per-thread neighbor indices (L2-resident, lanes dup-merge) ----
    int nidx[MT][9];
    #pragma unroll
    for (int m = 0; m < MT; m++) {
        int node = base + m*NG + g;
        #pragma unroll
        for (int j = 0; j < 9; j++)
            nidx[m][j] = neigh[node*9 + j] >> SHIFT;   // arithmetic shift keeps -1
    }

    __syncthreads();   // the only barrier: weights visible

    unsigned long long acc[MT][4];
    #pragma unroll
    for (int m = 0; m < MT; m++)
        #pragma unroll
        for (int p = 0; p < 4; p++) acc[m][p] = 0ull;

    #pragma unroll 1
    for (int j = 0; j < 9; j++) {
        const float4* pf[MT];
        #pragma unroll
        for (int m = 0; m < MT; m++) {
            int n = nidx[m][j];
            pf[m] = (n < 0) ? (const float4*)g_zero
                            : (const float4*)(feat + (size_t)n * CIN);
        }
        #pragma unroll
        for (int ch = 0; ch < NCH; ch++) {
            float4 cv[MT][CH];
            #pragma unroll
            for (int m = 0; m < MT; m++)
                #pragma unroll
                for (int c = 0; c < CH; c++)
                    cv[m][c] = pf[m][ch*CH + c];
            #pragma unroll
            for (int c = 0; c < CH; c++) {
                #pragma unroll
                for (int u = 0; u < 4; u++) {
                    const int k = j*CIN + (ch*CH + c)*4 + u;
                    const ulonglong2 wA = *(const ulonglong2*)&swt[k*SW + c0];
                    const ulonglong2 wB = *(const ulonglong2*)&swt[k*SW + c0 + 4];
                    #pragma unroll
                    for (int m = 0; m < MT; m++) {
                        float v = (u==0) ? cv[m][c].x : (u==1) ? cv[m][c].y
                                 : (u==2) ? cv[m][c].z : cv[m][c].w;
                        unsigned long long vv = pack2(v, v);
                        ffma2(acc[m][0], vv, wA.x);
                        ffma2(acc[m][1], vv, wA.y);
                        ffma2(acc[m][2], vv, wB.x);
                        ffma2(acc[m][3], vv, wB.y);
                    }
                }
            }
        }
    }

    // ---- epilogue ----
    const float4 bv0 = *(const float4*)&b[c0];
    const float4 bv1 = *(const float4*)&b[c0 + 4];
    #pragma unroll
    for (int m = 0; m < MT; m++) {
        int node = base + m*NG + g;
        float4 r0, r1;
        unpack2(r0.x, r0.y, acc[m][0]);
        unpack2(r0.z, r0.w, acc[m][1]);
        unpack2(r1.x, r1.y, acc[m][2]);
        unpack2(r1.z, r1.w, acc[m][3]);
        r0.x += bv0.x; r0.y += bv0.y; r0.z += bv0.z; r0.w += bv0.w;
        r1.x += bv1.x; r1.y += bv1.y; r1.z += bv1.z; r1.w += bv1.w;
        if (RELU) {
            r0.x = fmaxf(r0.x, 0.f); r0.y = fmaxf(r0.y, 0.f);
            r0.z = fmaxf(r0.z, 0.f); r0.w = fmaxf(r0.w, 0.f);
            r1.x = fmaxf(r1.x, 0.f); r1.y = fmaxf(r1.y, 0.f);
            r1.z = fmaxf(r1.z, 0.f); r1.w = fmaxf(r1.w, 0.f);
        }
        *(float4*)&out[node*COUT + c0]     = r0;
        *(float4*)&out[node*COUT + c0 + 4] = r1;
    }
}

// =====================================================================
// Generic conv (enc1 CIN=1 and head COUT=1 edge layers)
// =====================================================================
template<int CIN,int COUT,int TILE,int NT,int SHIFT,bool RELU>
__global__ __launch_bounds__(NT)
void conv_k(const float* __restrict__ feat, const int* __restrict__ neigh,
            const float* __restrict__ w, const float* __restrict__ b,
            float* __restrict__ out)
{
    constexpr int K   = 9*CIN;
    constexpr int VEC = (CIN % 4 == 0) ? 4 : 1;
    constexpr int STRIDE = (VEC == 4) ? (K + 4) : ((K % 2 == 0) ? (K + 1) : K);
    constexpr int TPN   = NT / TILE;
    constexpr int CO_PER = COUT / TPN;

    extern __shared__ float sm[];
    float* swt  = sm;
    float* scol = sm + K*COUT;
    __shared__ int sneigh[TILE*9];

    const int tid  = threadIdx.x;
    const int base = blockIdx.x * TILE;

    for (int i = tid; i < K*COUT; i += NT) {
        int k = i / COUT, c = i % COUT;
        swt[i] = w[c*K + k];
    }
    for (int i = tid; i < TILE*9; i += NT) {
        int n = neigh[(base + i/9)*9 + (i%9)];
        sneigh[i] = (n < 0) ? -1 : (n >> SHIFT);
    }
    __syncthreads();

    if (VEC == 4) {
        constexpr int KV = K / 4;
        constexpr int CVv = CIN / 4;
        const float4* f4 = (const float4*)feat;
        for (int e = tid; e < TILE*KV; e += NT) {
            int t = e / KV, r = e % KV;
            int j = r / CVv;
            int n = sneigh[t*9 + j];
            float4 v = (n < 0) ? make_float4(0.f,0.f,0.f,0.f) : f4[n*CVv + (r % CVv)];
            *(float4*)&scol[t*STRIDE + r*4] = v;
        }
    } else {
        for (int e = tid; e < TILE*K; e += NT) {
            int t = e / K, r = e % K;
            int j = r / CIN, ci = r % CIN;
            int n = sneigh[t*9 + j];
            scol[t*STRIDE + r] = (n < 0) ? 0.f : feat[n*CIN + ci];
        }
    }
    __syncthreads();

    const int t  = tid / TPN;
    const int c0 = (tid % TPN) * CO_PER;
    float acc[CO_PER];
    #pragma unroll
    for (int c = 0; c < CO_PER; c++) acc[c] = 0.f;

    const float* colrow = &scol[t*STRIDE];
    #pragma unroll 4
    for (int k = 0; k < K; k++) {
        float v = colrow[k];
        #pragma unroll
        for (int c = 0; c < CO_PER; c++)
            acc[c] += v * swt[k*COUT + c0 + c];
    }

    const int node = base + t;
    #pragma unroll
    for (int c = 0; c < CO_PER; c++) {
        float r = acc[c] + __ldg(&b[c0 + c]);
        if (RELU) r = fmaxf(r, 0.f);
        out[node*COUT + c0 + c] = r;
    }
}

// Max-pool over 4 consecutive child rows (dense keys -> parent = i>>2).
template<int C>
__global__ void pool_k(const float* __restrict__ in, float* __restrict__ out, int NP)
{
    int i = blockIdx.x * blockDim.x + threadIdx.x;
    int total = NP * (C/4);
    if (i >= total) return;
    int p = i / (C/4), cq = i % (C/4);
    const float4* in4 = (const float4*)in;
    float4 a = in4[(4*p+0)*(C/4)+cq];
    float4 b = in4[(4*p+1)*(C/4)+cq];
    float4 c = in4[(4*p+2)*(C/4)+cq];
    float4 d = in4[(4*p+3)*(C/4)+cq];
    float4 r;
    r.x = fmaxf(fmaxf(a.x,b.x), fmaxf(c.x,d.x));
    r.y = fmaxf(fmaxf(a.y,b.y), fmaxf(c.y,d.y));
    r.z = fmaxf(fmaxf(a.z,b.z), fmaxf(c.z,d.z));
    r.w = fmaxf(fmaxf(a.w,b.w), fmaxf(c.w,d.w));
    ((float4*)out)[i] = r;
}

// smem sizes: conv5 stages all weights once: KFULL * (COUT+4) floats
template<int CIN,int COUT>
static constexpr int conv5_smem() { return 9*CIN*(COUT+4)*4; }
static constexpr int SM_ENC2 = conv5_smem<16,32>();   // 20.7 KB
static constexpr int SM_ENC3 = conv5_smem<32,64>();   // 78.3 KB
static constexpr int SM_DEC1 = conv5_smem<64,32>();   // 82.9 KB
static constexpr int SM_DEC2 = conv5_smem<32,16>();   // 23.0 KB
static constexpr int SM1 = (9*1*16   + 256*9  ) * 4;
static constexpr int SM6 = (9*16*1   + 128*148) * 4;

extern "C" void kernel_launch(void* const* d_in, const int* in_sizes, int n_in,
                              void* d_out, int out_size)
{
    const float* features = (const float*)d_in[0];
    const int* neighs3 = (const int*)d_in[4];
    const int* neighs2 = (const int*)d_in[5];
    const int* neighs1 = (const int*)d_in[6];
    const float* w_enc1 = (const float*)d_in[7];
    const float* b_enc1 = (const float*)d_in[8];
    const float* w_enc2 = (const float*)d_in[9];
    const float* b_enc2 = (const float*)d_in[10];
    const float* w_enc3 = (const float*)d_in[11];
    const float* b_enc3 = (const float*)d_in[12];
    const float* w_dec1 = (const float*)d_in[13];
    const float* b_dec1 = (const float*)d_in[14];
    const float* w_dec2 = (const float*)d_in[15];
    const float* b_dec2 = (const float*)d_in[16];
    const float* w_head = (const float*)d_in[17];
    const float* b_head = (const float*)d_in[18];
    float* out = (float*)d_out;

    float *x8, *x7p, *x7, *x6p, *x6, *x7d, *x8d;
    cudaGetSymbolAddress((void**)&x8,  g_x8);
    cudaGetSymbolAddress((void**)&x7p, g_x7p);
    cudaGetSymbolAddress((void**)&x7,  g_x7);
    cudaGetSymbolAddress((void**)&x6p, g_x6p);
    cudaGetSymbolAddress((void**)&x6,  g_x6);
    cudaGetSymbolAddress((void**)&x7d, g_x7d);
    cudaGetSymbolAddress((void**)&x8d, g_x8d);

    cudaFuncSetAttribute((const void*)conv_k<1,16,256,256,0,true>,   cudaFuncAttributeMaxDynamicSharedMemorySize, SM1);
    cudaFuncSetAttribute((const void*)conv5_k<16,32,256,2,0,true>,   cudaFuncAttributeMaxDynamicSharedMemorySize, SM_ENC2);
    cudaFuncSetAttribute((const void*)conv5_k<32,64,256,2,0,true>,   cudaFuncAttributeMaxDynamicSharedMemorySize, SM_ENC3);
    cudaFuncSetAttribute((const void*)conv5_k<64,32,256,2,2,true>,   cudaFuncAttributeMaxDynamicSharedMemorySize, SM_DEC1);
    cudaFuncSetAttribute((const void*)conv5_k<32,16,256,2,2,true>,   cudaFuncAttributeMaxDynamicSharedMemorySize, SM_DEC2);
    cudaFuncSetAttribute((const void*)conv_k<16,1,128,128,0,false>,  cudaFuncAttributeMaxDynamicSharedMemorySize, SM6);

    // enc1: [N3,1] -> x8 [N3,16]
    conv_k<1,16,256,256,0,true><<<NN3/256, 256, SM1>>>(features, neighs3, w_enc1, b_enc1, x8);
    // pool: x8 -> x7p [N2,16]
    pool_k<16><<<(NN2*4 + 255)/256, 256>>>(x8, x7p, NN2);
    // enc2: x7p -> x7 [N2,32]   (OUTG=4, NG=64, TILE=128)
    conv5_k<16,32,256,2,0,true><<<NN2/128, 256, SM_ENC2>>>(x7p, neighs2, w_enc2, b_enc2, x7);
    // pool: x7 -> x6p [N1,32]
    pool_k<32><<<(NN1*8 + 255)/256, 256>>>(x7, x6p, NN1);
    // enc3: x6p -> x6 [N1,64]   (OUTG=8, NG=32, TILE=64)
    conv5_k<32,64,256,2,0,true><<<NN1/64, 256, SM_ENC3>>>(x6p, neighs1, w_enc3, b_enc3, x6);
    // dec1 (fused unpool via neigh>>2): x6 -> x7d [N2,32]   (OUTG=4, NG=64, TILE=128)
    conv5_k<64,32,256,2,2,true><<<NN2/128, 256, SM_DEC1>>>(x6, neighs2, w_dec1, b_dec1, x7d);
    // dec2 (fused unpool): x7d -> x8d [N3,16]   (OUTG=2, NG=128, TILE=256)
    conv5_k<32,16,256,2,2,true><<<NN3/256, 256, SM_DEC2>>>(x7d, neighs3, w_dec2, b_dec2, x8d);
    // head: x8d -> out [N3,1]
    conv_k<16,1,128,128,0,false><<<NN3/128, 128, SM6>>>(x8d, neighs3, w_head, b_head, out);
}

// round 13
// speedup vs baseline: 1.1370x; 1.1370x over previous
#include <cuda_runtime.h>
#include <cstdint>

#define NN3 262144
#define NN2 65536
#define NN1 16384

// Scratch (static device globals; no allocation allowed)
__device__ __align__(256) float g_x8 [NN3*16];
__device__ __align__(256) float g_x7p[NN2*16];
__device__ __align__(256) float g_x7 [NN2*32];
__device__ __align__(256) float g_x6p[NN1*32];
__device__ __align__(256) float g_x6 [NN1*64];
__device__ __align__(256) float g_x7d[NN2*32];
__device__ __align__(256) float g_x8d[NN3*16];

// zero row for -1 neighbors (max row = 64 floats = 256B)
__device__ __align__(256) float g_zero[64] = {0.f};

// ---------------- packed f32x2 helpers ----------------
__device__ __forceinline__ unsigned long long pack2(float x, float y) {
    unsigned long long r;
    asm("mov.b64 %0, {%1, %2};" : "=l"(r) : "f"(x), "f"(y));
    return r;
}
__device__ __forceinline__ void unpack2(float& x, float& y, unsigned long long v) {
    asm("mov.b64 {%0, %1}, %2;" : "=f"(x), "=f"(y) : "l"(v));
}
__device__ __forceinline__ void ffma2(unsigned long long& d, unsigned long long a, unsigned long long b) {
    asm("fma.rn.f32x2 %0, %1, %2, %0;" : "+l"(d) : "l"(a), "l"(b));
}

// ---------------- mbarrier helpers ----------------
__device__ __forceinline__ void mbar_init(uint32_t addr, uint32_t count) {
    asm volatile("mbarrier.init.shared.b64 [%0], %1;" :: "r"(addr), "r"(count) : "memory");
}
__device__ __forceinline__ void mbar_expect(uint32_t addr, uint32_t bytes) {
    asm volatile("mbarrier.arrive.expect_tx.shared.b64 _, [%0], %1;"
                 :: "r"(addr), "r"(bytes) : "memory");
}
__device__ __forceinline__ void mbar_wait(uint32_t addr, uint32_t parity) {
    asm volatile(
        "{\n\t"
        ".reg .pred P;\n"
        "LW_%=:\n\t"
        "mbarrier.try_wait.parity.acquire.cta.shared::cta.b64 P, [%0], %1, 0x989680;\n\t"
        "@P bra LD_%=;\n\t"
        "bra LW_%=;\n"
        "LD_%=:\n\t"
        "}"
        :: "r"(addr), "r"(parity) : "memory");
}
// one-row bulk copy: global -> shared::cta, completion counted on mbar
__device__ __forceinline__ void bulk_row(uint32_t dst, const void* src, uint32_t bytes, uint32_t mbar) {
    asm volatile("cp.async.bulk.shared::cta.global.mbarrier::complete_tx::bytes [%0], [%1], %2, [%3];"
                 :: "r"(dst), "l"(src), "r"(bytes), "r"(mbar) : "memory");
}

// =====================================================================
// conv6_k: bulk-engine gather conv GEMM.
//   - per-neighbor feature rows fetched with ONE cp.async.bulk each
//   - rows stored at pitch ROWB+16 (non-overlapping; odd quad stride ->
//     conflict-free compute LDS.128)
//   - double-buffered col tiles, mbarrier tx-count completion
//   - all 9 neighbors' weights staged transposed into smem once
//   - MOV-free fma.rn.f32x2 inner loop
// Thread map: og = tid % OUTG (8 outputs), g = tid / OUTG; MT nodes/thread.
// =====================================================================
template<int CIN,int COUT,int NT,int MT,int SHIFT,bool RELU>
__global__ __launch_bounds__(NT)
void conv6_k(const float* __restrict__ feat, const int* __restrict__ neigh,
             const float* __restrict__ w, const float* __restrict__ b,
             float* __restrict__ out)
{
    constexpr int NTC   = 8;
    constexpr int OUTG  = COUT / NTC;
    constexpr int NG    = NT / OUTG;
    constexpr int TILE  = MT * NG;
    static_assert(TILE <= NT, "one issuing thread per row");
    constexpr int KFULL = 9 * CIN;
    constexpr int SW    = COUT + 4;              // swt row stride; SW*4 % 16 == 0
    constexpr int ROWB  = CIN * 4;               // bytes per feature row
    constexpr int PITCH = ROWB + 16;             // padded row pitch (odd quad stride)
    static_assert((PITCH % 16) == 0, "pitch 16B granule");
    constexpr int BUF   = TILE * PITCH;          // buffer bytes
    constexpr int CV    = CIN / 4;
    constexpr uint32_t STAGE_BYTES = (uint32_t)TILE * ROWB;   // tx counts bytes copied

    // smem layout (byte offsets, all 16B aligned)
    constexpr int OFF_MBAR = 0;                  // 2 x 8B
    constexpr int OFF_W    = 16;
    constexpr int OFF_COL  = OFF_W + KFULL*SW*4;
    constexpr int OFF_NEI  = OFF_COL + 2*BUF;

    extern __shared__ __align__(16) unsigned char smraw[];
    float* swt    = (float*)(smraw + OFF_W);
    int*   sneigh = (int*)(smraw + OFF_NEI);
    const uint32_t smem0   = (uint32_t)__cvta_generic_to_shared(smraw);
    const uint32_t mbar_u  = smem0 + OFF_MBAR;
    const uint32_t col_u   = smem0 + OFF_COL;

    const int tid  = threadIdx.x;
    const int base = blockIdx.x * TILE;

    if (tid == 0) {
        mbar_init(mbar_u, 1); mbar_init(mbar_u + 8, 1);
        // expect for stages 0 and 1 BEFORE the barrier that releases issuers
        mbar_expect(mbar_u,     STAGE_BYTES);
        mbar_expect(mbar_u + 8, STAGE_BYTES);
    }

    // neighbor indices (arithmetic shift keeps -1)
    #pragma unroll 2
    for (int i = tid; i < TILE*9; i += NT)
        sneigh[i] = neigh[base*9 + i] >> SHIFT;

    // stage ALL weights transposed
    #pragma unroll 4
    for (int i = tid; i < KFULL*COUT; i += NT) {
        int c = i / KFULL, k = i % KFULL;
        swt[k*SW + c] = w[i];
    }
    __syncthreads();   // mbars(+expects) + sneigh + weights visible

    // ---- issue stages 0 and 1 ----
    #pragma unroll 1
    for (int s = 0; s < 2; s++) {
        if (tid < TILE) {
            int n = sneigh[tid*9 + s];
            const void* src = (n < 0) ? (const void*)g_zero : (const void*)(feat + (size_t)n*CIN);
            bulk_row(col_u + s*BUF + tid*PITCH, src, ROWB, mbar_u + s*8);
        }
    }

    const int og = tid % OUTG;
    const int g  = tid / OUTG;
    const int c0 = og * NTC;

    unsigned long long acc[MT][4];
    #pragma unroll
    for (int m = 0; m < MT; m++)
        #pragma unroll
        for (int p = 0; p < 4; p++) acc[m][p] = 0ull;

    #pragma unroll 1
    for (int s = 0; s < 9; s++) {
        const int bi = s & 1;
        mbar_wait(mbar_u + bi*8, (s >> 1) & 1);

        // ---- compute stage s ----
        const unsigned char* colb = smraw + OFF_COL + bi*BUF;
        const unsigned char* rp[MT];
        #pragma unroll
        for (int m = 0; m < MT; m++)
            rp[m] = colb + (m*NG + g)*PITCH;
        #pragma unroll
        for (int ci4 = 0; ci4 < CV; ci4++) {
            float4 cv[MT];
            #pragma unroll
            for (int m = 0; m < MT; m++)
                cv[m] = *(const float4*)(rp[m] + ci4*16);
            #pragma unroll
            for (int u = 0; u < 4; u++) {
                const int k = s*CIN + ci4*4 + u;
                const ulonglong2 wA = *(const ulonglong2*)&swt[k*SW + c0];
                const ulonglong2 wB = *(const ulonglong2*)&swt[k*SW + c0 + 4];
                #pragma unroll
                for (int m = 0; m < MT; m++) {
                    float v = (u==0) ? cv[m].x : (u==1) ? cv[m].y : (u==2) ? cv[m].z : cv[m].w;
                    unsigned long long vv = pack2(v, v);
                    ffma2(acc[m][0], vv, wA.x);
                    ffma2(acc[m][1], vv, wA.y);
                    ffma2(acc[m][2], vv, wB.x);
                    ffma2(acc[m][3], vv, wB.y);
                }
            }
        }
        __syncthreads();   // everyone done reading buffer bi

        // ---- prefetch stage s+2 into buffer bi ----
        if (s + 2 <= 8) {
            if (tid == 0) mbar_expect(mbar_u + bi*8, STAGE_BYTES);
            if (tid < TILE) {
                int n = sneigh[tid*9 + (s+2)];
                const void* src = (n < 0) ? (const void*)g_zero : (const void*)(feat + (size_t)n*CIN);
                bulk_row(col_u + bi*BUF + tid*PITCH, src, ROWB, mbar_u + bi*8);
            }
        }
    }

    // ---- epilogue ----
    const float4 bv0 = *(const float4*)&b[c0];
    const float4 bv1 = *(const float4*)&b[c0 + 4];
    #pragma unroll
    for (int m = 0; m < MT; m++) {
        int node = base + m*NG + g;
        float4 r0, r1;
        unpack2(r0.x, r0.y, acc[m][0]);
        unpack2(r0.z, r0.w, acc[m][1]);
        unpack2(r1.x, r1.y, acc[m][2]);
        unpack2(r1.z, r1.w, acc[m][3]);
        r0.x += bv0.x; r0.y += bv0.y; r0.z += bv0.z; r0.w += bv0.w;
        r1.x += bv1.x; r1.y += bv1.y; r1.z += bv1.z; r1.w += bv1.w;
        if (RELU) {
            r0.x = fmaxf(r0.x, 0.f); r0.y = fmaxf(r0.y, 0.f);
            r0.z = fmaxf(r0.z, 0.f); r0.w = fmaxf(r0.w, 0.f);
            r1.x = fmaxf(r1.x, 0.f); r1.y = fmaxf(r1.y, 0.f);
            r1.z = fmaxf(r1.z, 0.f); r1.w = fmaxf(r1.w, 0.f);
        }
        *(float4*)&out[node*COUT + c0]     = r0;
        *(float4*)&out[node*COUT + c0 + 4] = r1;
    }
}

// =====================================================================
// Generic conv (enc1 CIN=1 and head COUT=1 edge layers)
// =====================================================================
template<int CIN,int COUT,int TILE,int NT,int SHIFT,bool RELU>
__global__ __launch_bounds__(NT)
void conv_k(const float* __restrict__ feat, const int* __restrict__ neigh,
            const float* __restrict__ w, const float* __restrict__ b,
            float* __restrict__ out)
{
    constexpr int K   = 9*CIN;
    constexpr int VEC = (CIN % 4 == 0) ? 4 : 1;
    constexpr int STRIDE = (VEC == 4) ? (K + 4) : ((K % 2 == 0) ? (K + 1) : K);
    constexpr int TPN   = NT / TILE;
    constexpr int CO_PER = COUT / TPN;

    extern __shared__ float sm[];
    float* swt  = sm;
    float* scol = sm + K*COUT;
    __shared__ int sneigh[TILE*9];

    const int tid  = threadIdx.x;
    const int base = blockIdx.x * TILE;

    for (int i = tid; i < K*COUT; i += NT) {
        int k = i / COUT, c = i % COUT;
        swt[i] = w[c*K + k];
    }
    for (int i = tid; i < TILE*9; i += NT) {
        int n = neigh[(base + i/9)*9 + (i%9)];
        sneigh[i] = (n < 0) ? -1 : (n >> SHIFT);
    }
    __syncthreads();

    if (VEC == 4) {
        constexpr int KV = K / 4;
        constexpr int CVv = CIN / 4;
        const float4* f4 = (const float4*)feat;
        for (int e = tid; e < TILE*KV; e += NT) {
            int t = e / KV, r = e % KV;
            int j = r / CVv;
            int n = sneigh[t*9 + j];
            float4 v = (n < 0) ? make_float4(0.f,0.f,0.f,0.f) : f4[n*CVv + (r % CVv)];
            *(float4*)&scol[t*STRIDE + r*4] = v;
        }
    } else {
        for (int e = tid; e < TILE*K; e += NT) {
            int t = e / K, r = e % K;
            int j = r / CIN, ci = r % CIN;
            int n = sneigh[t*9 + j];
            scol[t*STRIDE + r] = (n < 0) ? 0.f : feat[n*CIN + ci];
        }
    }
    __syncthreads();

    const int t  = tid / TPN;
    const int c0 = (tid % TPN) * CO_PER;
    float acc[CO_PER];
    #pragma unroll
    for (int c = 0; c < CO_PER; c++) acc[c] = 0.f;

    const float* colrow = &scol[t*STRIDE];
    #pragma unroll 4
    for (int k = 0; k < K; k++) {
        float v = colrow[k];
        #pragma unroll
        for (int c = 0; c < CO_PER; c++)
            acc[c] += v * swt[k*COUT + c0 + c];
    }

    const int node = base + t;
    #pragma unroll
    for (int c = 0; c < CO_PER; c++) {
        float r = acc[c] + __ldg(&b[c0 + c]);
        if (RELU) r = fmaxf(r, 0.f);
        out[node*COUT + c0 + c] = r;
    }
}

// Max-pool over 4 consecutive child rows (dense keys -> parent = i>>2).
template<int C>
__global__ void pool_k(const float* __restrict__ in, float* __restrict__ out, int NP)
{
    int i = blockIdx.x * blockDim.x + threadIdx.x;
    int total = NP * (C/4);
    if (i >= total) return;
    int p = i / (C/4), cq = i % (C/4);
    const float4* in4 = (const float4*)in;
    float4 a = in4[(4*p+0)*(C/4)+cq];
    float4 b = in4[(4*p+1)*(C/4)+cq];
    float4 c = in4[(4*p+2)*(C/4)+cq];
    float4 d = in4[(4*p+3)*(C/4)+cq];
    float4 r;
    r.x = fmaxf(fmaxf(a.x,b.x), fmaxf(c.x,d.x));
    r.y = fmaxf(fmaxf(a.y,b.y), fmaxf(c.y,d.y));
    r.z = fmaxf(fmaxf(a.z,b.z), fmaxf(c.z,d.z));
    r.w = fmaxf(fmaxf(a.w,b.w), fmaxf(c.w,d.w));
    ((float4*)out)[i] = r;
}

// smem sizes for conv6: 16 (mbar) + weights + 2 pitched col buffers + sneigh
template<int CIN,int COUT,int NT,int MT>
static constexpr int conv6_smem() {
    constexpr int OUTG = COUT/8, NG = NT/OUTG, TILE = MT*NG;
    return 16 + 9*CIN*(COUT+4)*4 + 2*TILE*(CIN*4 + 16) + TILE*9*4;
}
static constexpr int SM_ENC2 = conv6_smem<16,32,256,2>();   // ~46 KB  (TILE=128)
static constexpr int SM_ENC3 = conv6_smem<32,64,256,2>();   // ~97 KB  (TILE=64)
static constexpr int SM_DEC1 = conv6_smem<64,32,256,2>();   // ~154 KB (TILE=128)
static constexpr int SM_DEC2 = conv6_smem<32,16,256,2>();   // ~103 KB (TILE=256)
static constexpr int SM1 = (9*1*16   + 256*9  ) * 4;
static constexpr int SM6 = (9*16*1   + 128*148) * 4;

extern "C" void kernel_launch(void* const* d_in, const int* in_sizes, int n_in,
                              void* d_out, int out_size)
{
    const float* features = (const float*)d_in[0];
    const int* neighs3 = (const int*)d_in[4];
    const int* neighs2 = (const int*)d_in[5];
    const int* neighs1 = (const int*)d_in[6];
    const float* w_enc1 = (const float*)d_in[7];
    const float* b_enc1 = (const float*)d_in[8];
    const float* w_enc2 = (const float*)d_in[9];
    const float* b_enc2 = (const float*)d_in[10];
    const float* w_enc3 = (const float*)d_in[11];
    const float* b_enc3 = (const float*)d_in[12];
    const float* w_dec1 = (const float*)d_in[13];
    const float* b_dec1 = (const float*)d_in[14];
    const float* w_dec2 = (const float*)d_in[15];
    const float* b_dec2 = (const float*)d_in[16];
    const float* w_head = (const float*)d_in[17];
    const float* b_head = (const float*)d_in[18];
    float* out = (float*)d_out;

    float *x8, *x7p, *x7, *x6p, *x6, *x7d, *x8d;
    cudaGetSymbolAddress((void**)&x8,  g_x8);
    cudaGetSymbolAddress((void**)&x7p, g_x7p);
    cudaGetSymbolAddress((void**)&x7,  g_x7);
    cudaGetSymbolAddress((void**)&x6p, g_x6p);
    cudaGetSymbolAddress((void**)&x6,  g_x6);
    cudaGetSymbolAddress((void**)&x7d, g_x7d);
    cudaGetSymbolAddress((void**)&x8d, g_x8d);

    cudaFuncSetAttribute((const void*)conv_k<1,16,256,256,0,true>,   cudaFuncAttributeMaxDynamicSharedMemorySize, SM1);
    cudaFuncSetAttribute((const void*)conv6_k<16,32,256,2,0,true>,   cudaFuncAttributeMaxDynamicSharedMemorySize, SM_ENC2);
    cudaFuncSetAttribute((const void*)conv6_k<32,64,256,2,0,true>,   cudaFuncAttributeMaxDynamicSharedMemorySize, SM_ENC3);
    cudaFuncSetAttribute((const void*)conv6_k<64,32,256,2,2,true>,   cudaFuncAttributeMaxDynamicSharedMemorySize, SM_DEC1);
    cudaFuncSetAttribute((const void*)conv6_k<32,16,256,2,2,true>,   cudaFuncAttributeMaxDynamicSharedMemorySize, SM_DEC2);
    cudaFuncSetAttribute((const void*)conv_k<16,1,128,128,0,false>,  cudaFuncAttributeMaxDynamicSharedMemorySize, SM6);

    // enc1: [N3,1] -> x8 [N3,16]
    conv_k<1,16,256,256,0,true><<<NN3/256, 256, SM1>>>(features, neighs3, w_enc1, b_enc1, x8);
    // pool: x8 -> x7p [N2,16]
    pool_k<16><<<(NN2*4 + 255)/256, 256>>>(x8, x7p, NN2);
    // enc2: x7p -> x7 [N2,32]   (TILE=128)
    conv6_k<16,32,256,2,0,true><<<NN2/128, 256, SM_ENC2>>>(x7p, neighs2, w_enc2, b_enc2, x7);
    // pool: x7 -> x6p [N1,32]
    pool_k<32><<<(NN1*8 + 255)/256, 256>>>(x7, x6p, NN1);
    // enc3: x6p -> x6 [N1,64]   (TILE=64)
    conv6_k<32,64,256,2,0,true><<<NN1/64, 256, SM_ENC3>>>(x6p, neighs1, w_enc3, b_enc3, x6);
    // dec1 (fused unpool via neigh>>2): x6 -> x7d [N2,32]   (TILE=128)
    conv6_k<64,32,256,2,2,true><<<NN2/128, 256, SM_DEC1>>>(x6, neighs2, w_dec1, b_dec1, x7d);
    // dec2 (fused unpool): x7d -> x8d [N3,16]   (TILE=256)
    conv6_k<32,16,256,2,2,true><<<NN3/256, 256, SM_DEC2>>>(x7d, neighs3, w_dec2, b_dec2, x8d);
    // head: x8d -> out [N3,1]
    conv_k<16,1,128,128,0,false><<<NN3/128, 128, SM6>>>(x8d, neighs3, w_head, b_head, out);
}